// round 15
// baseline (speedup 1.0000x reference)
#include <cuda_runtime.h>
#include <cuda_bf16.h>
#include <cstdint>
#include <math.h>

#define E_DIM 1024
#define NHEAD 16
#define HDIM  64
#define BATCH 2
#define SEQ   2048
#define MROWS (BATCH * SEQ)   // 4096

// ---------------- bf16 hi/lo plane scratch (lo plane at +N elements) --------
__device__ uint16_t g_xb  [2u * MROWS * E_DIM];
__device__ uint16_t g_rotT[2u * E_DIM * E_DIM];
__device__ uint16_t g_entT[2u * E_DIM * E_DIM];
__device__ uint16_t g_wqT [2u * E_DIM * E_DIM];
__device__ uint16_t g_wkT [2u * E_DIM * E_DIM];
__device__ uint16_t g_wv  [2u * E_DIM * E_DIM];
__device__ uint16_t g_wout[2u * E_DIM * E_DIM];
__device__ uint16_t g_wpq [2u * E_DIM * E_DIM];
__device__ uint16_t g_wpk [2u * E_DIM * E_DIM];
__device__ uint16_t g_qp  [2u * MROWS * E_DIM];
__device__ uint16_t g_kp  [2u * MROWS * E_DIM];
__device__ uint16_t g_v   [2u * MROWS * E_DIM];
__device__ uint16_t g_ob  [2u * MROWS * E_DIM];
__device__ float    g_bq  [E_DIM];
__device__ float    g_bk  [E_DIM];
__device__ float    g_bpart[2 * 16 * E_DIM];
__device__ float    g_fpart[4u * E_DIM * E_DIM];

// ======================= helpers ============================================
__device__ __forceinline__ uint32_t smem_u32(const void* p) {
    uint32_t a;
    asm("{ .reg .u64 t; cvta.to.shared.u64 t, %1; cvt.u32.u64 %0, t; }" : "=r"(a) : "l"(p));
    return a;
}
__device__ __forceinline__ void ldsm_x4(uint32_t* r, uint32_t addr) {
    asm volatile("ldmatrix.sync.aligned.m8n8.x4.shared.b16 {%0,%1,%2,%3}, [%4];"
                 : "=r"(r[0]), "=r"(r[1]), "=r"(r[2]), "=r"(r[3]) : "r"(addr));
}
__device__ __forceinline__ void ldsm_x4t(uint32_t* r, uint32_t addr) {
    asm volatile("ldmatrix.sync.aligned.m8n8.x4.trans.shared.b16 {%0,%1,%2,%3}, [%4];"
                 : "=r"(r[0]), "=r"(r[1]), "=r"(r[2]), "=r"(r[3]) : "r"(addr));
}
__device__ __forceinline__ void mma_bf16(float* c, const uint32_t* a, const uint32_t* b) {
    asm volatile(
        "mma.sync.aligned.m16n8k16.row.col.f32.bf16.bf16.f32 "
        "{%0,%1,%2,%3}, {%4,%5,%6,%7}, {%8,%9}, {%0,%1,%2,%3};"
        : "+f"(c[0]), "+f"(c[1]), "+f"(c[2]), "+f"(c[3])
        : "r"(a[0]), "r"(a[1]), "r"(a[2]), "r"(a[3]), "r"(b[0]), "r"(b[1]));
}
__device__ __forceinline__ void split1(float v, uint16_t& h, uint16_t& l) {
    __nv_bfloat16 hb = __float2bfloat16_rn(v);
    float r = v - __bfloat162float(hb);
    __nv_bfloat16 lb = __float2bfloat16_rn(r);
    h = *reinterpret_cast<uint16_t*>(&hb);
    l = *reinterpret_cast<uint16_t*>(&lb);
}
__device__ __forceinline__ void pack2(float a, float b, uint32_t& hi, uint32_t& lo) {
    uint16_t ha, la, hb, lb;
    split1(a, ha, la);
    split1(b, hb, lb);
    hi = (uint32_t)ha | ((uint32_t)hb << 16);
    lo = (uint32_t)la | ((uint32_t)lb << 16);
}
__device__ __forceinline__ uint32_t packhi2(float a, float b) {
    uint32_t r;
    asm("cvt.rn.bf16x2.f32 %0, %1, %2;" : "=r"(r) : "f"(b), "f"(a));
    return r;
}
__device__ __forceinline__ void cp16(uint32_t dst, const void* src) {
    asm volatile("cp.async.cg.shared.global [%0], [%1], 16;" :: "r"(dst), "l"(src));
}
#define CP_COMMIT() asm volatile("cp.async.commit_group;" ::: "memory")
#define CP_WAIT1()  asm volatile("cp.async.wait_group 1;" ::: "memory")
#define CP_WAIT0()  asm volatile("cp.async.wait_group 0;" ::: "memory")

// ======================= convert / fold kernels =============================
__global__ void conv_split3(const float* __restrict__ s0, uint16_t* __restrict__ d0, int n0,
                            const float* __restrict__ s1, uint16_t* __restrict__ d1, int n1,
                            const float* __restrict__ s2, uint16_t* __restrict__ d2, int n2)
{
    const float* src = (blockIdx.z == 0) ? s0 : (blockIdx.z == 1) ? s1 : s2;
    uint16_t* dst    = (blockIdx.z == 0) ? d0 : (blockIdx.z == 1) ? d1 : d2;
    const int n      = (blockIdx.z == 0) ? n0 : (blockIdx.z == 1) ? n1 : n2;
    int n4 = n >> 2;
    for (int i = blockIdx.x * blockDim.x + threadIdx.x; i < n4; i += gridDim.x * blockDim.x) {
        float4 v = ((const float4*)src)[i];
        uint32_t h0, l0, h1, l1;
        pack2(v.x, v.y, h0, l0);
        pack2(v.z, v.w, h1, l1);
        ((uint2*)dst)[i] = make_uint2(h0, h1);
        ((uint2*)(dst + n))[i] = make_uint2(l0, l1);
    }
}
__global__ void convT_split4(const float* __restrict__ s0, uint16_t* __restrict__ d0,
                             const float* __restrict__ s1, uint16_t* __restrict__ d1,
                             const float* __restrict__ s2, uint16_t* __restrict__ d2,
                             const float* __restrict__ s3, uint16_t* __restrict__ d3)
{
    const float* src = (blockIdx.z == 0) ? s0 : (blockIdx.z == 1) ? s1 : (blockIdx.z == 2) ? s2 : s3;
    uint16_t* dst    = (blockIdx.z == 0) ? d0 : (blockIdx.z == 1) ? d1 : (blockIdx.z == 2) ? d2 : d3;
    __shared__ float t[32][33];
    const int tx = threadIdx.x, ty = threadIdx.y;
    const int n0 = blockIdx.x * 32, k0 = blockIdx.y * 32;
#pragma unroll
    for (int j = 0; j < 4; j++)
        t[ty * 4 + j][tx] = src[(size_t)(k0 + ty * 4 + j) * E_DIM + n0 + tx];
    __syncthreads();
#pragma unroll
    for (int j = 0; j < 4; j++) {
        int n = n0 + ty * 4 + j, k = k0 + tx;
        uint16_t h, l;
        split1(t[tx][ty * 4 + j], h, l);
        dst[(size_t)n * E_DIM + k] = h;
        dst[(size_t)E_DIM * E_DIM + (size_t)n * E_DIM + k] = l;
    }
}
__global__ void bias_fold_part(const float* __restrict__ b0, const float* __restrict__ R0,
                               const float* __restrict__ b1, const float* __restrict__ R1,
                               float* __restrict__ part)
{
    const int z = blockIdx.z;
    const int n = blockIdx.x * 256 + threadIdx.x;
    const int s = blockIdx.y;
    const float* bin = z ? b1 : b0;
    const float* R   = z ? R1 : R0;
    float acc = 0.f;
    const int m0 = s * 64;
#pragma unroll 8
    for (int m = m0; m < m0 + 64; m++)
        acc = fmaf(bin[m], R[(size_t)m * E_DIM + n], acc);
    part[(size_t)(z * 16 + s) * E_DIM + n] = acc;
}
__global__ void bias_fold_red(const float* __restrict__ part,
                              float* __restrict__ o0, float sc0,
                              float* __restrict__ o1, float sc1)
{
    const int z = blockIdx.z;
    const int n = blockIdx.x * 256 + threadIdx.x;
    float acc = 0.f;
#pragma unroll
    for (int s = 0; s < 16; s++)
        acc += part[(size_t)(z * 16 + s) * E_DIM + n];
    (z ? o1 : o0)[n] = acc * (z ? sc1 : sc0);
}
__global__ void fold_red(const float* __restrict__ part,
                         uint16_t* __restrict__ wpq, float sc0,
                         uint16_t* __restrict__ wpk, float sc1)
{
    const int z = blockIdx.z;
    const size_t NW = (size_t)E_DIM * E_DIM;
    const float4* p0 = (const float4*)(part + (size_t)(2 * z) * NW);
    const float4* p1 = (const float4*)(part + (size_t)(2 * z + 1) * NW);
    uint16_t* Ph = z ? wpk : wpq;
    uint16_t* Pl = Ph + NW;
    const float sc = z ? sc1 : sc0;
    const int n4 = (int)(NW >> 2);
    for (int i = blockIdx.x * blockDim.x + threadIdx.x; i < n4; i += gridDim.x * blockDim.x) {
        float4 a = p0[i], b = p1[i];
        float4 v = make_float4((a.x + b.x) * sc, (a.y + b.y) * sc,
                               (a.z + b.z) * sc, (a.w + b.w) * sc);
        uint32_t h0, l0, h1, l1;
        pack2(v.x, v.y, h0, l0);
        pack2(v.z, v.w, h1, l1);
        ((uint2*)Ph)[i] = make_uint2(h0, h1);
        ((uint2*)Pl)[i] = make_uint2(l0, l1);
    }
}

// ======================= bf16-plane HMMA GEMM (cp.async 2-stage) ============
#define SROWB 80
#define GPLANE (128 * SROWB)
#define GSTAGE (4 * GPLANE)
#define GEMM_SMEM (2 * GSTAGE)
#define PAH 0
#define PAL GPLANE
#define PBH (2 * GPLANE)
#define PBL (3 * GPLANE)

#define GEMM_BODY(AH, AL, LDA, BH, BL, LDB, BM, BN, KTOT, T3)                          \
    float acc[4][4][4];                                                                \
    _Pragma("unroll")                                                                  \
    for (int i = 0; i < 4; i++)                                                        \
        _Pragma("unroll")                                                              \
        for (int j = 0; j < 4; j++)                                                    \
            _Pragma("unroll")                                                          \
            for (int t = 0; t < 4; t++) acc[i][j][t] = 0.f;                            \
    const uint32_t a4r = (uint32_t)((wm * 64 + (lane & 15)) * SROWB + (lane >> 4) * 16);\
    const uint32_t b4r = (uint32_t)((wn * 32 + (lane & 7)) * SROWB + ((lane >> 3) & 1) * 16 + (lane >> 4) * 32);\
    const int nchunks = (KTOT) / 32;                                                   \
    auto stage_load = [&](int k0, uint32_t sst) {                                      \
        _Pragma("unroll")                                                              \
        for (int it = 0; it < 8; it++) {                                               \
            int idx = tid + it * 256;                                                  \
            int plane = idx >> 9;                                                      \
            int rem = idx & 511;                                                       \
            int row = rem >> 2;                                                        \
            int q = rem & 3;                                                           \
            if (!(T3) && plane == 1) continue;                                         \
            const uint16_t* src;                                                       \
            if (plane == 0)      src = (AH) + (size_t)((BM) + row) * (LDA) + k0 + q * 8;\
            else if (plane == 1) src = (AL) + (size_t)((BM) + row) * (LDA) + k0 + q * 8;\
            else if (plane == 2) src = (BH) + (size_t)((BN) + row) * (LDB) + k0 + q * 8;\
            else                 src = (BL) + (size_t)((BN) + row) * (LDB) + k0 + q * 8;\
            cp16(sst + (uint32_t)(plane * GPLANE + row * SROWB + q * 16), src);        \
        }                                                                              \
        CP_COMMIT();                                                                   \
    };                                                                                 \
    stage_load(0, sbase);                                                              \
    if (nchunks > 1) stage_load(32, sbase + GSTAGE);                                   \
    for (int c = 0; c < nchunks; c++) {                                                \
        if (c + 1 < nchunks) { CP_WAIT1(); } else { CP_WAIT0(); }                      \
        __syncthreads();                                                               \
        const uint32_t ss = sbase + (uint32_t)((c & 1) * GSTAGE);                      \
        uint32_t bh4[4][4], bl4[4][4];                                                 \
        _Pragma("unroll")                                                              \
        for (int nt = 0; nt < 4; nt++) {                                               \
            ldsm_x4(bh4[nt], ss + b4r + nt * 8 * SROWB + PBH);                         \
            ldsm_x4(bl4[nt], ss + b4r + nt * 8 * SROWB + PBL);                         \
        }                                                                              \
        _Pragma("unroll")                                                              \
        for (int ks = 0; ks < 2; ks++) {                                               \
            uint32_t ah[4][4], al[4][4];                                               \
            _Pragma("unroll")                                                          \
            for (int mt = 0; mt < 4; mt++) {                                           \
                ldsm_x4(ah[mt], ss + a4r + mt * 16 * SROWB + ks * 32 + PAH);           \
                if (T3) ldsm_x4(al[mt], ss + a4r + mt * 16 * SROWB + ks * 32 + PAL);   \
            }                                                                          \
            _Pragma("unroll")                                                          \
            for (int mt = 0; mt < 4; mt++)                                             \
                _Pragma("unroll")                                                      \
                for (int nt = 0; nt < 4; nt++) {                                       \
                    mma_bf16(acc[mt][nt], ah[mt], &bh4[nt][2 * ks]);                   \
                    mma_bf16(acc[mt][nt], ah[mt], &bl4[nt][2 * ks]);                   \
                    if (T3) mma_bf16(acc[mt][nt], al[mt], &bh4[nt][2 * ks]);           \
                }                                                                      \
        }                                                                              \
        __syncthreads();                                                               \
        if (c + 2 < nchunks) stage_load((c + 2) * 32, sbase + (uint32_t)((c & 1) * GSTAGE));\
    }

template<int MODE>
__global__ __launch_bounds__(256)
void hgemm_bf16(const uint16_t* __restrict__ Ah, const uint16_t* __restrict__ Al, int lda,
                const uint16_t* __restrict__ Bh, const uint16_t* __restrict__ Bl, int ldb,
                const float* __restrict__ bias,
                const float* __restrict__ res, int ldr,
                float* __restrict__ C, int ldc,
                uint16_t* __restrict__ P0h, uint16_t* __restrict__ P0l, int ldp,
                float scale, int K)
{
    extern __shared__ char smem[];
    const uint32_t sbase = smem_u32(smem);
    const int tid  = threadIdx.x;
    const int lane = tid & 31;
    const int wid  = tid >> 5;
    const int wm   = wid >> 2;
    const int wn   = wid & 3;
    const int bm   = blockIdx.y * 128;
    const int bn   = blockIdx.x * 128;

    GEMM_BODY(Ah, Al, lda, Bh, Bl, ldb, bm, bn, K, 0)

#pragma unroll
    for (int mt = 0; mt < 4; mt++) {
#pragma unroll
        for (int nt = 0; nt < 4; nt++) {
            const int m0 = bm + wm * 64 + mt * 16 + (lane >> 2);
            const int n0 = bn + wn * 32 + nt * 8 + 2 * (lane & 3);
            float2 v0 = make_float2(acc[mt][nt][0], acc[mt][nt][1]);
            float2 v1 = make_float2(acc[mt][nt][2], acc[mt][nt][3]);
            if (MODE == 0) {
                float2 bb = *(const float2*)(bias + n0);
                float2 r0 = *(const float2*)(res + (size_t)m0 * ldr + n0);
                float2 r1 = *(const float2*)(res + (size_t)(m0 + 8) * ldr + n0);
                v0.x += bb.x + r0.x; v0.y += bb.y + r0.y;
                v1.x += bb.x + r1.x; v1.y += bb.y + r1.y;
                *(float2*)(C + (size_t)m0 * ldc + n0) = v0;
                *(float2*)(C + (size_t)(m0 + 8) * ldc + n0) = v1;
            } else {
                v0.x *= scale; v0.y *= scale;
                v1.x *= scale; v1.y *= scale;
                uint32_t h0, l0, h1, l1;
                pack2(v0.x, v0.y, h0, l0);
                pack2(v1.x, v1.y, h1, l1);
                *(uint32_t*)(P0h + (size_t)m0 * ldp + n0) = h0;
                *(uint32_t*)(P0l + (size_t)m0 * ldp + n0) = l0;
                *(uint32_t*)(P0h + (size_t)(m0 + 8) * ldp + n0) = h1;
                *(uint32_t*)(P0l + (size_t)(m0 + 8) * ldp + n0) = l1;
            }
        }
    }
}

__global__ __launch_bounds__(256)
void hgemm_fold_part(const uint16_t* __restrict__ rotT, const uint16_t* __restrict__ entT,
                     const uint16_t* __restrict__ wqT,  const uint16_t* __restrict__ wkT,
                     float* __restrict__ fpart)
{
    extern __shared__ char smem[];
    const uint32_t sbase = smem_u32(smem);
    const int tid  = threadIdx.x;
    const int lane = tid & 31;
    const int wid  = tid >> 5;
    const int wm   = wid >> 2;
    const int wn   = wid & 3;
    const int bm   = blockIdx.y * 128;
    const int bn   = blockIdx.x * 128;
    const int z    = blockIdx.z;
    const int fz   = z >> 1;
    const int ky   = z & 1;
    const size_t NW = (size_t)E_DIM * E_DIM;

    const uint16_t* Ah = (fz ? entT : rotT) + ky * 512;
    const uint16_t* Bh = (fz ? wkT : wqT) + ky * 512;
    const uint16_t* Al = Ah + NW;
    const uint16_t* Bl = Bh + NW;
    float* P = fpart + (size_t)z * NW;

    GEMM_BODY(Ah, Al, E_DIM, Bh, Bl, E_DIM, bm, bn, 512, 1)

#pragma unroll
    for (int mt = 0; mt < 4; mt++) {
#pragma unroll
        for (int nt = 0; nt < 4; nt++) {
            const int m0 = bm + wm * 64 + mt * 16 + (lane >> 2);
            const int n0 = bn + wn * 32 + nt * 8 + 2 * (lane & 3);
            *(float2*)(P + (size_t)m0 * E_DIM + n0) =
                make_float2(acc[mt][nt][0], acc[mt][nt][1]);
            *(float2*)(P + (size_t)(m0 + 8) * E_DIM + n0) =
                make_float2(acc[mt][nt][2], acc[mt][nt][3]);
        }
    }
}

__global__ __launch_bounds__(256)
void hgemm_qkv(const uint16_t* __restrict__ Ah, const uint16_t* __restrict__ Al,
               const uint16_t* __restrict__ Bqh, const uint16_t* __restrict__ Bql,
               const uint16_t* __restrict__ Bkh, const uint16_t* __restrict__ Bkl,
               const uint16_t* __restrict__ Bvh, const uint16_t* __restrict__ Bvl,
               const float* __restrict__ biasq, const float* __restrict__ biask,
               const float* __restrict__ biasv,
               uint16_t* __restrict__ Pqh, uint16_t* __restrict__ Pql,
               uint16_t* __restrict__ Pkh, uint16_t* __restrict__ Pkl,
               uint16_t* __restrict__ Pvh, uint16_t* __restrict__ Pvl)
{
    extern __shared__ char smem[];
    const uint32_t sbase = smem_u32(smem);
    const int tid  = threadIdx.x;
    const int lane = tid & 31;
    const int wid  = tid >> 5;
    const int wm   = wid >> 2;
    const int wn   = wid & 3;
    const int bm   = blockIdx.y * 128;
    const int bn   = blockIdx.x * 128;
    const int part = bn >> 10;
    const int bnc  = bn & 1023;

    const uint16_t* Bh = (part == 0) ? Bqh : (part == 1) ? Bkh : Bvh;
    const uint16_t* Bl = (part == 0) ? Bql : (part == 1) ? Bkl : Bvl;
    const float* bias  = (part == 0) ? biasq : (part == 1) ? biask : biasv;
    uint16_t* Ph = (part == 0) ? Pqh : (part == 1) ? Pkh : Pvh;
    uint16_t* Pl = (part == 0) ? Pql : (part == 1) ? Pkl : Pvl;

    GEMM_BODY(Ah, Al, E_DIM, Bh, Bl, E_DIM, bm, bnc, E_DIM, 0)

#pragma unroll
    for (int mt = 0; mt < 4; mt++) {
#pragma unroll
        for (int nt = 0; nt < 4; nt++) {
            const int m0 = bm + wm * 64 + mt * 16 + (lane >> 2);
            const int n0 = bnc + wn * 32 + nt * 8 + 2 * (lane & 3);
            float2 bb = *(const float2*)(bias + n0);
            float2 v0 = make_float2(acc[mt][nt][0] + bb.x, acc[mt][nt][1] + bb.y);
            float2 v1 = make_float2(acc[mt][nt][2] + bb.x, acc[mt][nt][3] + bb.y);
            uint32_t h0, l0, h1, l1;
            pack2(v0.x, v0.y, h0, l0);
            pack2(v1.x, v1.y, h1, l1);
            *(uint32_t*)(Ph + (size_t)m0 * E_DIM + n0) = h0;
            *(uint32_t*)(Pl + (size_t)m0 * E_DIM + n0) = l0;
            *(uint32_t*)(Ph + (size_t)(m0 + 8) * E_DIM + n0) = h1;
            *(uint32_t*)(Pl + (size_t)(m0 + 8) * E_DIM + n0) = l1;
        }
    }
}

// ======================= HMMA flash attention (pipelined S vs softmax) =======
#define TROWB 144
#define FPLANE (64 * TROWB)
#define FSTAGE (4 * FPLANE)
#define FLASH_SMEM (2 * FSTAGE)
#define QKH 0
#define QKL FPLANE
#define QVH (2 * FPLANE)
#define QVL (3 * FPLANE)
#define NKT (SEQ / 64)

__global__ __launch_bounds__(128)
void flash_bf16(const uint16_t* __restrict__ Qh, const uint16_t* __restrict__ Ql,
                const uint16_t* __restrict__ Kh, const uint16_t* __restrict__ Kl,
                const uint16_t* __restrict__ Vh, const uint16_t* __restrict__ Vl,
                uint16_t* __restrict__ Oh, uint16_t* __restrict__ Ol)
{
    extern __shared__ char smem[];
    const uint32_t sbase = smem_u32(smem);

    const int tid  = threadIdx.x;
    const int lane = tid & 31;
    const int w    = tid >> 5;
    const int h = blockIdx.y;
    const int b = blockIdx.z;
    const int bq = blockIdx.x * 64;

    const size_t qrow0 = (size_t)(b * SEQ + bq);
    const size_t krow0 = (size_t)b * SEQ;
    const int hc = h * HDIM;

    {
        const int r  = tid >> 1;
        const int c8h = (tid & 1) * 4;
#pragma unroll
        for (int g = 0; g < 4; g++) {
            const uint16_t* src = Qh + (qrow0 + r) * E_DIM + hc + (c8h + g) * 8;
            *(uint4*)(smem + r * TROWB + (c8h + g) * 16 + QKH) = *(const uint4*)src;
        }
    }
    __syncthreads();

    uint32_t qh[4][4];
    {
        const uint32_t a_off = sbase + (uint32_t)((w * 16 + (lane & 15)) * TROWB + (lane >> 4) * 16);
#pragma unroll
        for (int ks = 0; ks < 4; ks++)
            ldsm_x4(qh[ks], a_off + QKH + ks * 32);
    }
    __syncthreads();

    float o[8][4];
#pragma unroll
    for (int nt = 0; nt < 8; nt++)
#pragma unroll
        for (int t = 0; t < 4; t++) o[nt][t] = 0.f;
    float mrow[2] = {-1e30f, -1e30f};
    float lrow[2] = {0.f, 0.f};

    const uint32_t kb4r = (uint32_t)((lane & 7) * TROWB + ((lane >> 3) & 1) * 16 + (lane >> 4) * 32);
    const uint32_t vb4r = (uint32_t)(((lane & 7) + ((lane >> 3) & 1) * 8) * TROWB + (lane >> 4) * 16);

    auto stage_kv = [&](int j0, uint32_t sst) {
#pragma unroll
        for (int it = 0; it < 16; it++) {
            int idx = tid + it * 128;
            int plane = idx >> 9;
            int rem = idx & 511;
            int row = rem >> 3;
            int q = rem & 7;
            const size_t g = (krow0 + j0 + row) * (size_t)E_DIM + hc + q * 8;
            const uint16_t* src;
            if (plane == 0)      src = Kh + g;
            else if (plane == 1) src = Kl + g;
            else if (plane == 2) src = Vh + g;
            else                 src = Vl + g;
            cp16(sst + (uint32_t)(plane * FPLANE + row * TROWB + q * 16), src);
        }
        CP_COMMIT();
    };

    // compute S for tile at slot ss into dst
    auto compute_S = [&](uint32_t ss, float (*dst)[4]) {
#pragma unroll
        for (int nt = 0; nt < 8; nt++)
#pragma unroll
            for (int t = 0; t < 4; t++) dst[nt][t] = 0.f;
#pragma unroll
        for (int ksp = 0; ksp < 2; ksp++) {
#pragma unroll
            for (int nt = 0; nt < 8; nt++) {
                uint32_t bd = ss + kb4r + (uint32_t)(nt * 8 * TROWB + ksp * 64);
                uint32_t bh[4], bl[4];
                ldsm_x4(bh, bd + QKH);
                ldsm_x4(bl, bd + QKL);
                mma_bf16(dst[nt], qh[2 * ksp],     bh);
                mma_bf16(dst[nt], qh[2 * ksp],     bl);
                mma_bf16(dst[nt], qh[2 * ksp + 1], bh + 2);
                mma_bf16(dst[nt], qh[2 * ksp + 1], bl + 2);
            }
        }
    };

    stage_kv(0, sbase);
    stage_kv(64, sbase + FSTAGE);

    float s_cur[8][4], s_next[8][4];

    // prologue: tile 0 ready -> S(0)
    CP_WAIT1();
    __syncthreads();
    compute_S(sbase, s_cur);

    for (int c = 0; c < NKT; c++) {
        const uint32_t ss_cur = sbase + (uint32_t)((c & 1) * FSTAGE);

        // ---- issue S(c+1) MMAs first (independent of softmax below) --------
        if (c + 1 < NKT) {
            CP_WAIT0();          // tile c+1 is the only outstanding group
            __syncthreads();
            compute_S(sbase + (uint32_t)(((c + 1) & 1) * FSTAGE), s_next);
        }

        // ---- softmax(c) on s_cur (overlaps with in-flight S MMAs) -----------
#pragma unroll
        for (int rr = 0; rr < 2; rr++) {
            const int off = 2 * rr;
            float mx = s_cur[0][off];
#pragma unroll
            for (int nt = 0; nt < 8; nt++) {
                mx = fmaxf(mx, s_cur[nt][off]);
                mx = fmaxf(mx, s_cur[nt][off + 1]);
            }
            mx = fmaxf(mx, __shfl_xor_sync(0xffffffffu, mx, 1));
            mx = fmaxf(mx, __shfl_xor_sync(0xffffffffu, mx, 2));
            float mnew = fmaxf(mrow[rr], mx);
            float sc = __expf(mrow[rr] - mnew);
            mrow[rr] = mnew;
            float sum = 0.f;
#pragma unroll
            for (int nt = 0; nt < 8; nt++) {
                s_cur[nt][off]     = __expf(s_cur[nt][off]     - mnew);
                s_cur[nt][off + 1] = __expf(s_cur[nt][off + 1] - mnew);
                sum += s_cur[nt][off] + s_cur[nt][off + 1];
            }
            sum += __shfl_xor_sync(0xffffffffu, sum, 1);
            sum += __shfl_xor_sync(0xffffffffu, sum, 2);
            lrow[rr] = lrow[rr] * sc + sum;
#pragma unroll
            for (int nt = 0; nt < 8; nt++) {
                o[nt][off]     *= sc;
                o[nt][off + 1] *= sc;
            }
        }

        // ---- O += P V  (V from slot c — not yet overwritten) ---------------
#pragma unroll
        for (int ks = 0; ks < 4; ks++) {
            uint32_t pa[4];
            pa[0] = packhi2(s_cur[2 * ks][0],     s_cur[2 * ks][1]);
            pa[1] = packhi2(s_cur[2 * ks][2],     s_cur[2 * ks][3]);
            pa[2] = packhi2(s_cur[2 * ks + 1][0], s_cur[2 * ks + 1][1]);
            pa[3] = packhi2(s_cur[2 * ks + 1][2], s_cur[2 * ks + 1][3]);
#pragma unroll
            for (int nt2 = 0; nt2 < 4; nt2++) {
                uint32_t vd = ss_cur + vb4r + (uint32_t)(ks * 16 * TROWB + nt2 * 32);
                uint32_t bh[4], bl[4];
                ldsm_x4t(bh, vd + QVH);
                ldsm_x4t(bl, vd + QVL);
                mma_bf16(o[2 * nt2], pa, bh);
                mma_bf16(o[2 * nt2], pa, bl);
                mma_bf16(o[2 * nt2 + 1], pa, bh + 2);
                mma_bf16(o[2 * nt2 + 1], pa, bl + 2);
            }
        }
        __syncthreads();   // all warps done reading slot c
        if (c + 2 < NKT) stage_kv((c + 2) * 64, ss_cur);

        // rotate fragments
#pragma unroll
        for (int nt = 0; nt < 8; nt++)
#pragma unroll
            for (int t = 0; t < 4; t++) s_cur[nt][t] = s_next[nt][t];
    }

    const float inv0 = 1.f / lrow[0];
    const float inv1 = 1.f / lrow[1];
    const size_t m0 = qrow0 + w * 16 + (lane >> 2);
#pragma unroll
    for (int nt = 0; nt < 8; nt++) {
        const int n = hc + nt * 8 + 2 * (lane & 3);
        uint32_t h0, l0, h1, l1;
        pack2(o[nt][0] * inv0, o[nt][1] * inv0, h0, l0);
        pack2(o[nt][2] * inv1, o[nt][3] * inv1, h1, l1);
        *(uint32_t*)(Oh + m0 * E_DIM + n) = h0;
        *(uint32_t*)(Ol + m0 * E_DIM + n) = l0;
        *(uint32_t*)(Oh + (m0 + 8) * E_DIM + n) = h1;
        *(uint32_t*)(Ol + (m0 + 8) * E_DIM + n) = l1;
    }
}

// ---------------- launcher ---------------------------------------------------
extern "C" void kernel_launch(void* const* d_in, const int* in_sizes, int n_in,
                              void* d_out, int out_size)
{
    (void)in_sizes; (void)n_in; (void)out_size;
    const float* x    = (const float*)d_in[0];
    const float* rot  = (const float*)d_in[1];
    const float* ent  = (const float*)d_in[2];
    const float* qkvw = (const float*)d_in[3];
    const float* qkvb = (const float*)d_in[4];
    const float* outw = (const float*)d_in[5];
    const float* outb = (const float*)d_in[6];
    float* out = (float*)d_out;

    uint16_t *xb, *rotT, *entT, *wqT, *wkT, *wv, *wout, *wpq, *wpk, *qp, *kp, *v, *ob;
    float *bqf, *bkf, *bpart, *fpart;
    cudaGetSymbolAddress((void**)&xb,    g_xb);
    cudaGetSymbolAddress((void**)&rotT,  g_rotT);
    cudaGetSymbolAddress((void**)&entT,  g_entT);
    cudaGetSymbolAddress((void**)&wqT,   g_wqT);
    cudaGetSymbolAddress((void**)&wkT,   g_wkT);
    cudaGetSymbolAddress((void**)&wv,    g_wv);
    cudaGetSymbolAddress((void**)&wout,  g_wout);
    cudaGetSymbolAddress((void**)&wpq,   g_wpq);
    cudaGetSymbolAddress((void**)&wpk,   g_wpk);
    cudaGetSymbolAddress((void**)&qp,    g_qp);
    cudaGetSymbolAddress((void**)&kp,    g_kp);
    cudaGetSymbolAddress((void**)&v,     g_v);
    cudaGetSymbolAddress((void**)&ob,    g_ob);
    cudaGetSymbolAddress((void**)&bqf,   g_bq);
    cudaGetSymbolAddress((void**)&bkf,   g_bk);
    cudaGetSymbolAddress((void**)&bpart, g_bpart);
    cudaGetSymbolAddress((void**)&fpart, g_fpart);

    const int NX = MROWS * E_DIM;
    const int NW = E_DIM * E_DIM;

    cudaFuncSetAttribute(hgemm_bf16<0>,   cudaFuncAttributeMaxDynamicSharedMemorySize, GEMM_SMEM);
    cudaFuncSetAttribute(hgemm_fold_part, cudaFuncAttributeMaxDynamicSharedMemorySize, GEMM_SMEM);
    cudaFuncSetAttribute(hgemm_qkv,       cudaFuncAttributeMaxDynamicSharedMemorySize, GEMM_SMEM);
    cudaFuncSetAttribute(flash_bf16,      cudaFuncAttributeMaxDynamicSharedMemorySize, FLASH_SMEM);

    // 0) converts + bias folds
    conv_split3<<<dim3(384, 1, 3), 256>>>(x, xb, NX, qkvw + 2u * NW, wv, NW, outw, wout, NW);
    convT_split4<<<dim3(32, 32, 4), dim3(32, 8)>>>(
        rot, rotT, ent, entT, qkvw, wqT, qkvw + 1u * NW, wkT);
    bias_fold_part<<<dim3(4, 16, 2), 256>>>(qkvb, rot, qkvb + E_DIM, ent, bpart);
    bias_fold_red<<<dim3(4, 1, 2), 256>>>(bpart, bqf, 0.125f, bkf, 1.f);

    // 0c) split-K weight folds (3-term) + reduce
    hgemm_fold_part<<<dim3(8, 8, 4), 256, GEMM_SMEM>>>(rotT, entT, wqT, wkT, fpart);
    fold_red<<<dim3(192, 1, 2), 256>>>(fpart, wpq, 0.125f, wpk, 1.f);

    // 1) fused qkv GEMM (2-term) -> Q (rotated+scaled), K (entangled), V planes
    hgemm_qkv<<<dim3(3 * E_DIM / 128, MROWS / 128), 256, GEMM_SMEM>>>(
        xb, xb + NX,
        wpq, wpq + NW, wpk, wpk + NW, wv, wv + NW,
        bqf, bkf, qkvb + 2 * E_DIM,
        qp, qp + NX, kp, kp + NX, v, v + NX);

    // 2) attention -> O planes (pipelined)
    flash_bf16<<<dim3(SEQ / 64, NHEAD, BATCH), 128, FLASH_SMEM>>>(
        qp, qp + NX, kp, kp + NX, v, v + NX, ob, ob + NX);

    // 3) out = O @ out_w^T + out_b + x  (2-term)
    hgemm_bf16<0><<<dim3(E_DIM / 128, MROWS / 128), 256, GEMM_SMEM>>>(
        ob, ob + NX, E_DIM, wout, wout + NW, E_DIM,
        outb, x, E_DIM, out, E_DIM,
        nullptr, nullptr, 0, 1.f, E_DIM);
}

// round 17
// speedup vs baseline: 1.0709x; 1.0709x over previous
#include <cuda_runtime.h>
#include <cuda_bf16.h>
#include <cstdint>
#include <math.h>

#define E_DIM 1024
#define NHEAD 16
#define HDIM  64
#define BATCH 2
#define SEQ   2048
#define MROWS (BATCH * SEQ)   // 4096

// ---------------- bf16 hi/lo plane scratch (lo plane at +N elements) --------
__device__ uint16_t g_xb  [2u * MROWS * E_DIM];
__device__ uint16_t g_rotT[2u * E_DIM * E_DIM];
__device__ uint16_t g_entT[2u * E_DIM * E_DIM];
__device__ uint16_t g_wqT [2u * E_DIM * E_DIM];
__device__ uint16_t g_wkT [2u * E_DIM * E_DIM];
__device__ uint16_t g_wv  [2u * E_DIM * E_DIM];
__device__ uint16_t g_wout[2u * E_DIM * E_DIM];
__device__ uint16_t g_wpq [2u * E_DIM * E_DIM];
__device__ uint16_t g_wpk [2u * E_DIM * E_DIM];
__device__ uint16_t g_qp  [2u * MROWS * E_DIM];
__device__ uint16_t g_kp  [2u * MROWS * E_DIM];
__device__ uint16_t g_v   [2u * MROWS * E_DIM];
__device__ uint16_t g_ob  [2u * MROWS * E_DIM];
__device__ float    g_bq  [E_DIM];
__device__ float    g_bk  [E_DIM];
__device__ float    g_bpart[2 * 16 * E_DIM];
__device__ float    g_fpart[4u * E_DIM * E_DIM];

// ======================= helpers ============================================
__device__ __forceinline__ uint32_t smem_u32(const void* p) {
    uint32_t a;
    asm("{ .reg .u64 t; cvta.to.shared.u64 t, %1; cvt.u32.u64 %0, t; }" : "=r"(a) : "l"(p));
    return a;
}
__device__ __forceinline__ void ldsm_x4(uint32_t* r, uint32_t addr) {
    asm volatile("ldmatrix.sync.aligned.m8n8.x4.shared.b16 {%0,%1,%2,%3}, [%4];"
                 : "=r"(r[0]), "=r"(r[1]), "=r"(r[2]), "=r"(r[3]) : "r"(addr));
}
__device__ __forceinline__ void ldsm_x4t(uint32_t* r, uint32_t addr) {
    asm volatile("ldmatrix.sync.aligned.m8n8.x4.trans.shared.b16 {%0,%1,%2,%3}, [%4];"
                 : "=r"(r[0]), "=r"(r[1]), "=r"(r[2]), "=r"(r[3]) : "r"(addr));
}
__device__ __forceinline__ void mma_bf16(float* c, const uint32_t* a, const uint32_t* b) {
    asm volatile(
        "mma.sync.aligned.m16n8k16.row.col.f32.bf16.bf16.f32 "
        "{%0,%1,%2,%3}, {%4,%5,%6,%7}, {%8,%9}, {%0,%1,%2,%3};"
        : "+f"(c[0]), "+f"(c[1]), "+f"(c[2]), "+f"(c[3])
        : "r"(a[0]), "r"(a[1]), "r"(a[2]), "r"(a[3]), "r"(b[0]), "r"(b[1]));
}
__device__ __forceinline__ void split1(float v, uint16_t& h, uint16_t& l) {
    __nv_bfloat16 hb = __float2bfloat16_rn(v);
    float r = v - __bfloat162float(hb);
    __nv_bfloat16 lb = __float2bfloat16_rn(r);
    h = *reinterpret_cast<uint16_t*>(&hb);
    l = *reinterpret_cast<uint16_t*>(&lb);
}
__device__ __forceinline__ void pack2(float a, float b, uint32_t& hi, uint32_t& lo) {
    uint16_t ha, la, hb, lb;
    split1(a, ha, la);
    split1(b, hb, lb);
    hi = (uint32_t)ha | ((uint32_t)hb << 16);
    lo = (uint32_t)la | ((uint32_t)lb << 16);
}
__device__ __forceinline__ uint32_t packhi2(float a, float b) {
    uint32_t r;
    asm("cvt.rn.bf16x2.f32 %0, %1, %2;" : "=r"(r) : "f"(b), "f"(a));
    return r;
}
__device__ __forceinline__ void cp16(uint32_t dst, const void* src) {
    asm volatile("cp.async.cg.shared.global [%0], [%1], 16;" :: "r"(dst), "l"(src));
}
#define CP_COMMIT() asm volatile("cp.async.commit_group;" ::: "memory")
#define CP_WAIT1()  asm volatile("cp.async.wait_group 1;" ::: "memory")
#define CP_WAIT0()  asm volatile("cp.async.wait_group 0;" ::: "memory")

// ======================= convert / fold kernels =============================
__global__ void conv_split3(const float* __restrict__ s0, uint16_t* __restrict__ d0, int n0,
                            const float* __restrict__ s1, uint16_t* __restrict__ d1, int n1,
                            const float* __restrict__ s2, uint16_t* __restrict__ d2, int n2)
{
    const float* src = (blockIdx.z == 0) ? s0 : (blockIdx.z == 1) ? s1 : s2;
    uint16_t* dst    = (blockIdx.z == 0) ? d0 : (blockIdx.z == 1) ? d1 : d2;
    const int n      = (blockIdx.z == 0) ? n0 : (blockIdx.z == 1) ? n1 : n2;
    int n4 = n >> 2;
    for (int i = blockIdx.x * blockDim.x + threadIdx.x; i < n4; i += gridDim.x * blockDim.x) {
        float4 v = ((const float4*)src)[i];
        uint32_t h0, l0, h1, l1;
        pack2(v.x, v.y, h0, l0);
        pack2(v.z, v.w, h1, l1);
        ((uint2*)dst)[i] = make_uint2(h0, h1);
        ((uint2*)(dst + n))[i] = make_uint2(l0, l1);
    }
}
__global__ void convT_split4(const float* __restrict__ s0, uint16_t* __restrict__ d0,
                             const float* __restrict__ s1, uint16_t* __restrict__ d1,
                             const float* __restrict__ s2, uint16_t* __restrict__ d2,
                             const float* __restrict__ s3, uint16_t* __restrict__ d3)
{
    const float* src = (blockIdx.z == 0) ? s0 : (blockIdx.z == 1) ? s1 : (blockIdx.z == 2) ? s2 : s3;
    uint16_t* dst    = (blockIdx.z == 0) ? d0 : (blockIdx.z == 1) ? d1 : (blockIdx.z == 2) ? d2 : d3;
    __shared__ float t[32][33];
    const int tx = threadIdx.x, ty = threadIdx.y;
    const int n0 = blockIdx.x * 32, k0 = blockIdx.y * 32;
#pragma unroll
    for (int j = 0; j < 4; j++)
        t[ty * 4 + j][tx] = src[(size_t)(k0 + ty * 4 + j) * E_DIM + n0 + tx];
    __syncthreads();
#pragma unroll
    for (int j = 0; j < 4; j++) {
        int n = n0 + ty * 4 + j, k = k0 + tx;
        uint16_t h, l;
        split1(t[tx][ty * 4 + j], h, l);
        dst[(size_t)n * E_DIM + k] = h;
        dst[(size_t)E_DIM * E_DIM + (size_t)n * E_DIM + k] = l;
    }
}
__global__ void bias_fold_part(const float* __restrict__ b0, const float* __restrict__ R0,
                               const float* __restrict__ b1, const float* __restrict__ R1,
                               float* __restrict__ part)
{
    const int z = blockIdx.z;
    const int n = blockIdx.x * 256 + threadIdx.x;
    const int s = blockIdx.y;
    const float* bin = z ? b1 : b0;
    const float* R   = z ? R1 : R0;
    float acc = 0.f;
    const int m0 = s * 64;
#pragma unroll 8
    for (int m = m0; m < m0 + 64; m++)
        acc = fmaf(bin[m], R[(size_t)m * E_DIM + n], acc);
    part[(size_t)(z * 16 + s) * E_DIM + n] = acc;
}
__global__ void bias_fold_red(const float* __restrict__ part,
                              float* __restrict__ o0, float sc0,
                              float* __restrict__ o1, float sc1)
{
    const int z = blockIdx.z;
    const int n = blockIdx.x * 256 + threadIdx.x;
    float acc = 0.f;
#pragma unroll
    for (int s = 0; s < 16; s++)
        acc += part[(size_t)(z * 16 + s) * E_DIM + n];
    (z ? o1 : o0)[n] = acc * (z ? sc1 : sc0);
}
__global__ void fold_red(const float* __restrict__ part,
                         uint16_t* __restrict__ wpq, float sc0,
                         uint16_t* __restrict__ wpk, float sc1)
{
    const int z = blockIdx.z;
    const size_t NW = (size_t)E_DIM * E_DIM;
    const float4* p0 = (const float4*)(part + (size_t)(2 * z) * NW);
    const float4* p1 = (const float4*)(part + (size_t)(2 * z + 1) * NW);
    uint16_t* Ph = z ? wpk : wpq;
    uint16_t* Pl = Ph + NW;
    const float sc = z ? sc1 : sc0;
    const int n4 = (int)(NW >> 2);
    for (int i = blockIdx.x * blockDim.x + threadIdx.x; i < n4; i += gridDim.x * blockDim.x) {
        float4 a = p0[i], b = p1[i];
        float4 v = make_float4((a.x + b.x) * sc, (a.y + b.y) * sc,
                               (a.z + b.z) * sc, (a.w + b.w) * sc);
        uint32_t h0, l0, h1, l1;
        pack2(v.x, v.y, h0, l0);
        pack2(v.z, v.w, h1, l1);
        ((uint2*)Ph)[i] = make_uint2(h0, h1);
        ((uint2*)Pl)[i] = make_uint2(l0, l1);
    }
}

// ======================= bf16-plane HMMA GEMM (cp.async 2-stage) ============
#define SROWB 80
#define GPLANE (128 * SROWB)
#define GSTAGE (4 * GPLANE)
#define GEMM_SMEM (2 * GSTAGE)
#define PAH 0
#define PAL GPLANE
#define PBH (2 * GPLANE)
#define PBL (3 * GPLANE)

#define GEMM_BODY(AH, AL, LDA, BH, BL, LDB, BM, BN, KTOT, T3)                          \
    float acc[4][4][4];                                                                \
    _Pragma("unroll")                                                                  \
    for (int i = 0; i < 4; i++)                                                        \
        _Pragma("unroll")                                                              \
        for (int j = 0; j < 4; j++)                                                    \
            _Pragma("unroll")                                                          \
            for (int t = 0; t < 4; t++) acc[i][j][t] = 0.f;                            \
    const uint32_t a4r = (uint32_t)((wm * 64 + (lane & 15)) * SROWB + (lane >> 4) * 16);\
    const uint32_t b4r = (uint32_t)((wn * 32 + (lane & 7)) * SROWB + ((lane >> 3) & 1) * 16 + (lane >> 4) * 32);\
    const int nchunks = (KTOT) / 32;                                                   \
    auto stage_load = [&](int k0, uint32_t sst) {                                      \
        _Pragma("unroll")                                                              \
        for (int it = 0; it < 8; it++) {                                               \
            int idx = tid + it * 256;                                                  \
            int plane = idx >> 9;                                                      \
            int rem = idx & 511;                                                       \
            int row = rem >> 2;                                                        \
            int q = rem & 3;                                                           \
            if (!(T3) && plane == 1) continue;                                         \
            const uint16_t* src;                                                       \
            if (plane == 0)      src = (AH) + (size_t)((BM) + row) * (LDA) + k0 + q * 8;\
            else if (plane == 1) src = (AL) + (size_t)((BM) + row) * (LDA) + k0 + q * 8;\
            else if (plane == 2) src = (BH) + (size_t)((BN) + row) * (LDB) + k0 + q * 8;\
            else                 src = (BL) + (size_t)((BN) + row) * (LDB) + k0 + q * 8;\
            cp16(sst + (uint32_t)(plane * GPLANE + row * SROWB + q * 16), src);        \
        }                                                                              \
        CP_COMMIT();                                                                   \
    };                                                                                 \
    stage_load(0, sbase);                                                              \
    if (nchunks > 1) stage_load(32, sbase + GSTAGE);                                   \
    for (int c = 0; c < nchunks; c++) {                                                \
        if (c + 1 < nchunks) { CP_WAIT1(); } else { CP_WAIT0(); }                      \
        __syncthreads();                                                               \
        const uint32_t ss = sbase + (uint32_t)((c & 1) * GSTAGE);                      \
        uint32_t bh4[4][4], bl4[4][4];                                                 \
        _Pragma("unroll")                                                              \
        for (int nt = 0; nt < 4; nt++) {                                               \
            ldsm_x4(bh4[nt], ss + b4r + nt * 8 * SROWB + PBH);                         \
            ldsm_x4(bl4[nt], ss + b4r + nt * 8 * SROWB + PBL);                         \
        }                                                                              \
        _Pragma("unroll")                                                              \
        for (int ks = 0; ks < 2; ks++) {                                               \
            uint32_t ah[4][4], al[4][4];                                               \
            _Pragma("unroll")                                                          \
            for (int mt = 0; mt < 4; mt++) {                                           \
                ldsm_x4(ah[mt], ss + a4r + mt * 16 * SROWB + ks * 32 + PAH);           \
                if (T3) ldsm_x4(al[mt], ss + a4r + mt * 16 * SROWB + ks * 32 + PAL);   \
            }                                                                          \
            _Pragma("unroll")                                                          \
            for (int mt = 0; mt < 4; mt++)                                             \
                _Pragma("unroll")                                                      \
                for (int nt = 0; nt < 4; nt++) {                                       \
                    mma_bf16(acc[mt][nt], ah[mt], &bh4[nt][2 * ks]);                   \
                    mma_bf16(acc[mt][nt], ah[mt], &bl4[nt][2 * ks]);                   \
                    if (T3) mma_bf16(acc[mt][nt], al[mt], &bh4[nt][2 * ks]);           \
                }                                                                      \
        }                                                                              \
        __syncthreads();                                                               \
        if (c + 2 < nchunks) stage_load((c + 2) * 32, sbase + (uint32_t)((c & 1) * GSTAGE));\
    }

template<int MODE>
__global__ __launch_bounds__(256)
void hgemm_bf16(const uint16_t* __restrict__ Ah, const uint16_t* __restrict__ Al, int lda,
                const uint16_t* __restrict__ Bh, const uint16_t* __restrict__ Bl, int ldb,
                const float* __restrict__ bias,
                const float* __restrict__ res, int ldr,
                float* __restrict__ C, int ldc,
                uint16_t* __restrict__ P0h, uint16_t* __restrict__ P0l, int ldp,
                float scale, int K)
{
    extern __shared__ char smem[];
    const uint32_t sbase = smem_u32(smem);
    const int tid  = threadIdx.x;
    const int lane = tid & 31;
    const int wid  = tid >> 5;
    const int wm   = wid >> 2;
    const int wn   = wid & 3;
    const int bm   = blockIdx.y * 128;
    const int bn   = blockIdx.x * 128;

    GEMM_BODY(Ah, Al, lda, Bh, Bl, ldb, bm, bn, K, 0)

#pragma unroll
    for (int mt = 0; mt < 4; mt++) {
#pragma unroll
        for (int nt = 0; nt < 4; nt++) {
            const int m0 = bm + wm * 64 + mt * 16 + (lane >> 2);
            const int n0 = bn + wn * 32 + nt * 8 + 2 * (lane & 3);
            float2 v0 = make_float2(acc[mt][nt][0], acc[mt][nt][1]);
            float2 v1 = make_float2(acc[mt][nt][2], acc[mt][nt][3]);
            if (MODE == 0) {
                float2 bb = *(const float2*)(bias + n0);
                float2 r0 = *(const float2*)(res + (size_t)m0 * ldr + n0);
                float2 r1 = *(const float2*)(res + (size_t)(m0 + 8) * ldr + n0);
                v0.x += bb.x + r0.x; v0.y += bb.y + r0.y;
                v1.x += bb.x + r1.x; v1.y += bb.y + r1.y;
                *(float2*)(C + (size_t)m0 * ldc + n0) = v0;
                *(float2*)(C + (size_t)(m0 + 8) * ldc + n0) = v1;
            } else {
                v0.x *= scale; v0.y *= scale;
                v1.x *= scale; v1.y *= scale;
                uint32_t h0, l0, h1, l1;
                pack2(v0.x, v0.y, h0, l0);
                pack2(v1.x, v1.y, h1, l1);
                *(uint32_t*)(P0h + (size_t)m0 * ldp + n0) = h0;
                *(uint32_t*)(P0l + (size_t)m0 * ldp + n0) = l0;
                *(uint32_t*)(P0h + (size_t)(m0 + 8) * ldp + n0) = h1;
                *(uint32_t*)(P0l + (size_t)(m0 + 8) * ldp + n0) = l1;
            }
        }
    }
}

__global__ __launch_bounds__(256)
void hgemm_fold_part(const uint16_t* __restrict__ rotT, const uint16_t* __restrict__ entT,
                     const uint16_t* __restrict__ wqT,  const uint16_t* __restrict__ wkT,
                     float* __restrict__ fpart)
{
    extern __shared__ char smem[];
    const uint32_t sbase = smem_u32(smem);
    const int tid  = threadIdx.x;
    const int lane = tid & 31;
    const int wid  = tid >> 5;
    const int wm   = wid >> 2;
    const int wn   = wid & 3;
    const int bm   = blockIdx.y * 128;
    const int bn   = blockIdx.x * 128;
    const int z    = blockIdx.z;
    const int fz   = z >> 1;
    const int ky   = z & 1;
    const size_t NW = (size_t)E_DIM * E_DIM;

    const uint16_t* Ah = (fz ? entT : rotT) + ky * 512;
    const uint16_t* Bh = (fz ? wkT : wqT) + ky * 512;
    const uint16_t* Al = Ah + NW;
    const uint16_t* Bl = Bh + NW;
    float* P = fpart + (size_t)z * NW;

    GEMM_BODY(Ah, Al, E_DIM, Bh, Bl, E_DIM, bm, bn, 512, 1)

#pragma unroll
    for (int mt = 0; mt < 4; mt++) {
#pragma unroll
        for (int nt = 0; nt < 4; nt++) {
            const int m0 = bm + wm * 64 + mt * 16 + (lane >> 2);
            const int n0 = bn + wn * 32 + nt * 8 + 2 * (lane & 3);
            *(float2*)(P + (size_t)m0 * E_DIM + n0) =
                make_float2(acc[mt][nt][0], acc[mt][nt][1]);
            *(float2*)(P + (size_t)(m0 + 8) * E_DIM + n0) =
                make_float2(acc[mt][nt][2], acc[mt][nt][3]);
        }
    }
}

__global__ __launch_bounds__(256)
void hgemm_qkv(const uint16_t* __restrict__ Ah, const uint16_t* __restrict__ Al,
               const uint16_t* __restrict__ Bqh, const uint16_t* __restrict__ Bql,
               const uint16_t* __restrict__ Bkh, const uint16_t* __restrict__ Bkl,
               const uint16_t* __restrict__ Bvh, const uint16_t* __restrict__ Bvl,
               const float* __restrict__ biasq, const float* __restrict__ biask,
               const float* __restrict__ biasv,
               uint16_t* __restrict__ Pqh, uint16_t* __restrict__ Pql,
               uint16_t* __restrict__ Pkh, uint16_t* __restrict__ Pkl,
               uint16_t* __restrict__ Pvh, uint16_t* __restrict__ Pvl)
{
    extern __shared__ char smem[];
    const uint32_t sbase = smem_u32(smem);
    const int tid  = threadIdx.x;
    const int lane = tid & 31;
    const int wid  = tid >> 5;
    const int wm   = wid >> 2;
    const int wn   = wid & 3;
    const int bm   = blockIdx.y * 128;
    const int bn   = blockIdx.x * 128;
    const int part = bn >> 10;
    const int bnc  = bn & 1023;

    const uint16_t* Bh = (part == 0) ? Bqh : (part == 1) ? Bkh : Bvh;
    const uint16_t* Bl = (part == 0) ? Bql : (part == 1) ? Bkl : Bvl;
    const float* bias  = (part == 0) ? biasq : (part == 1) ? biask : biasv;
    uint16_t* Ph = (part == 0) ? Pqh : (part == 1) ? Pkh : Pvh;
    uint16_t* Pl = (part == 0) ? Pql : (part == 1) ? Pkl : Pvl;

    GEMM_BODY(Ah, Al, E_DIM, Bh, Bl, E_DIM, bm, bnc, E_DIM, 0)

#pragma unroll
    for (int mt = 0; mt < 4; mt++) {
#pragma unroll
        for (int nt = 0; nt < 4; nt++) {
            const int m0 = bm + wm * 64 + mt * 16 + (lane >> 2);
            const int n0 = bnc + wn * 32 + nt * 8 + 2 * (lane & 3);
            float2 bb = *(const float2*)(bias + n0);
            float2 v0 = make_float2(acc[mt][nt][0] + bb.x, acc[mt][nt][1] + bb.y);
            float2 v1 = make_float2(acc[mt][nt][2] + bb.x, acc[mt][nt][3] + bb.y);
            uint32_t h0, l0, h1, l1;
            pack2(v0.x, v0.y, h0, l0);
            pack2(v1.x, v1.y, h1, l1);
            *(uint32_t*)(Ph + (size_t)m0 * E_DIM + n0) = h0;
            *(uint32_t*)(Pl + (size_t)m0 * E_DIM + n0) = l0;
            *(uint32_t*)(Ph + (size_t)(m0 + 8) * E_DIM + n0) = h1;
            *(uint32_t*)(Pl + (size_t)(m0 + 8) * E_DIM + n0) = l1;
        }
    }
}

// ======================= HMMA flash attention (R14 body, 3 CTAs/SM) ==========
#define TROWB 144
#define FPLANE (64 * TROWB)
#define FSTAGE (4 * FPLANE)
#define FLASH_SMEM (2 * FSTAGE)
#define QKH 0
#define QKL FPLANE
#define QVH (2 * FPLANE)
#define QVL (3 * FPLANE)
#define NKT (SEQ / 64)

__global__ __launch_bounds__(128, 3)
void flash_bf16(const uint16_t* __restrict__ Qh, const uint16_t* __restrict__ Ql,
                const uint16_t* __restrict__ Kh, const uint16_t* __restrict__ Kl,
                const uint16_t* __restrict__ Vh, const uint16_t* __restrict__ Vl,
                uint16_t* __restrict__ Oh, uint16_t* __restrict__ Ol)
{
    extern __shared__ char smem[];
    const uint32_t sbase = smem_u32(smem);

    const int tid  = threadIdx.x;
    const int lane = tid & 31;
    const int w    = tid >> 5;
    const int h = blockIdx.y;
    const int b = blockIdx.z;
    const int bq = blockIdx.x * 64;

    const size_t qrow0 = (size_t)(b * SEQ + bq);
    const size_t krow0 = (size_t)b * SEQ;
    const int hc = h * HDIM;

    {
        const int r  = tid >> 1;
        const int c8h = (tid & 1) * 4;
#pragma unroll
        for (int g = 0; g < 4; g++) {
            const uint16_t* src = Qh + (qrow0 + r) * E_DIM + hc + (c8h + g) * 8;
            *(uint4*)(smem + r * TROWB + (c8h + g) * 16 + QKH) = *(const uint4*)src;
        }
    }
    __syncthreads();

    uint32_t qh[4][4];
    {
        const uint32_t a_off = sbase + (uint32_t)((w * 16 + (lane & 15)) * TROWB + (lane >> 4) * 16);
#pragma unroll
        for (int ks = 0; ks < 4; ks++)
            ldsm_x4(qh[ks], a_off + QKH + ks * 32);
    }
    __syncthreads();

    float o[8][4];
#pragma unroll
    for (int nt = 0; nt < 8; nt++)
#pragma unroll
        for (int t = 0; t < 4; t++) o[nt][t] = 0.f;
    float mrow[2] = {-1e30f, -1e30f};
    float lrow[2] = {0.f, 0.f};

    const uint32_t kb4r = (uint32_t)((lane & 7) * TROWB + ((lane >> 3) & 1) * 16 + (lane >> 4) * 32);
    const uint32_t vb4r = (uint32_t)(((lane & 7) + ((lane >> 3) & 1) * 8) * TROWB + (lane >> 4) * 16);

    auto stage_kv = [&](int j0, uint32_t sst) {
#pragma unroll
        for (int it = 0; it < 16; it++) {
            int idx = tid + it * 128;
            int plane = idx >> 9;
            int rem = idx & 511;
            int row = rem >> 3;
            int q = rem & 7;
            const size_t g = (krow0 + j0 + row) * (size_t)E_DIM + hc + q * 8;
            const uint16_t* src;
            if (plane == 0)      src = Kh + g;
            else if (plane == 1) src = Kl + g;
            else if (plane == 2) src = Vh + g;
            else                 src = Vl + g;
            cp16(sst + (uint32_t)(plane * FPLANE + row * TROWB + q * 16), src);
        }
        CP_COMMIT();
    };

    stage_kv(0, sbase);
    stage_kv(64, sbase + FSTAGE);

    for (int c = 0; c < NKT; c++) {
        if (c + 1 < NKT) { CP_WAIT1(); } else { CP_WAIT0(); }
        __syncthreads();
        const uint32_t ss = sbase + (uint32_t)((c & 1) * FSTAGE);

        float s[8][4];
#pragma unroll
        for (int nt = 0; nt < 8; nt++)
#pragma unroll
            for (int t = 0; t < 4; t++) s[nt][t] = 0.f;
#pragma unroll
        for (int ksp = 0; ksp < 2; ksp++) {
#pragma unroll
            for (int nt = 0; nt < 8; nt++) {
                uint32_t bd = ss + kb4r + (uint32_t)(nt * 8 * TROWB + ksp * 64);
                uint32_t bh[4], bl[4];
                ldsm_x4(bh, bd + QKH);
                ldsm_x4(bl, bd + QKL);
                mma_bf16(s[nt], qh[2 * ksp],     bh);
                mma_bf16(s[nt], qh[2 * ksp],     bl);
                mma_bf16(s[nt], qh[2 * ksp + 1], bh + 2);
                mma_bf16(s[nt], qh[2 * ksp + 1], bl + 2);
            }
        }

#pragma unroll
        for (int rr = 0; rr < 2; rr++) {
            const int off = 2 * rr;
            float mx = s[0][off];
#pragma unroll
            for (int nt = 0; nt < 8; nt++) {
                mx = fmaxf(mx, s[nt][off]);
                mx = fmaxf(mx, s[nt][off + 1]);
            }
            mx = fmaxf(mx, __shfl_xor_sync(0xffffffffu, mx, 1));
            mx = fmaxf(mx, __shfl_xor_sync(0xffffffffu, mx, 2));
            float mnew = fmaxf(mrow[rr], mx);
            float sc = __expf(mrow[rr] - mnew);
            mrow[rr] = mnew;
            float sum = 0.f;
#pragma unroll
            for (int nt = 0; nt < 8; nt++) {
                s[nt][off]     = __expf(s[nt][off]     - mnew);
                s[nt][off + 1] = __expf(s[nt][off + 1] - mnew);
                sum += s[nt][off] + s[nt][off + 1];
            }
            sum += __shfl_xor_sync(0xffffffffu, sum, 1);
            sum += __shfl_xor_sync(0xffffffffu, sum, 2);
            lrow[rr] = lrow[rr] * sc + sum;
#pragma unroll
            for (int nt = 0; nt < 8; nt++) {
                o[nt][off]     *= sc;
                o[nt][off + 1] *= sc;
            }
        }

#pragma unroll
        for (int ks = 0; ks < 4; ks++) {
            uint32_t pa[4];
            pa[0] = packhi2(s[2 * ks][0],     s[2 * ks][1]);
            pa[1] = packhi2(s[2 * ks][2],     s[2 * ks][3]);
            pa[2] = packhi2(s[2 * ks + 1][0], s[2 * ks + 1][1]);
            pa[3] = packhi2(s[2 * ks + 1][2], s[2 * ks + 1][3]);
#pragma unroll
            for (int nt2 = 0; nt2 < 4; nt2++) {
                uint32_t vd = ss + vb4r + (uint32_t)(ks * 16 * TROWB + nt2 * 32);
                uint32_t bh[4], bl[4];
                ldsm_x4t(bh, vd + QVH);
                ldsm_x4t(bl, vd + QVL);
                mma_bf16(o[2 * nt2], pa, bh);
                mma_bf16(o[2 * nt2], pa, bl);
                mma_bf16(o[2 * nt2 + 1], pa, bh + 2);
                mma_bf16(o[2 * nt2 + 1], pa, bl + 2);
            }
        }
        __syncthreads();
        if (c + 2 < NKT) stage_kv((c + 2) * 64, sbase + (uint32_t)((c & 1) * FSTAGE));
    }

    const float inv0 = 1.f / lrow[0];
    const float inv1 = 1.f / lrow[1];
    const size_t m0 = qrow0 + w * 16 + (lane >> 2);
#pragma unroll
    for (int nt = 0; nt < 8; nt++) {
        const int n = hc + nt * 8 + 2 * (lane & 3);
        uint32_t h0, l0, h1, l1;
        pack2(o[nt][0] * inv0, o[nt][1] * inv0, h0, l0);
        pack2(o[nt][2] * inv1, o[nt][3] * inv1, h1, l1);
        *(uint32_t*)(Oh + m0 * E_DIM + n) = h0;
        *(uint32_t*)(Ol + m0 * E_DIM + n) = l0;
        *(uint32_t*)(Oh + (m0 + 8) * E_DIM + n) = h1;
        *(uint32_t*)(Ol + (m0 + 8) * E_DIM + n) = l1;
    }
}

// ---------------- launcher ---------------------------------------------------
extern "C" void kernel_launch(void* const* d_in, const int* in_sizes, int n_in,
                              void* d_out, int out_size)
{
    (void)in_sizes; (void)n_in; (void)out_size;
    const float* x    = (const float*)d_in[0];
    const float* rot  = (const float*)d_in[1];
    const float* ent  = (const float*)d_in[2];
    const float* qkvw = (const float*)d_in[3];
    const float* qkvb = (const float*)d_in[4];
    const float* outw = (const float*)d_in[5];
    const float* outb = (const float*)d_in[6];
    float* out = (float*)d_out;

    uint16_t *xb, *rotT, *entT, *wqT, *wkT, *wv, *wout, *wpq, *wpk, *qp, *kp, *v, *ob;
    float *bqf, *bkf, *bpart, *fpart;
    cudaGetSymbolAddress((void**)&xb,    g_xb);
    cudaGetSymbolAddress((void**)&rotT,  g_rotT);
    cudaGetSymbolAddress((void**)&entT,  g_entT);
    cudaGetSymbolAddress((void**)&wqT,   g_wqT);
    cudaGetSymbolAddress((void**)&wkT,   g_wkT);
    cudaGetSymbolAddress((void**)&wv,    g_wv);
    cudaGetSymbolAddress((void**)&wout,  g_wout);
    cudaGetSymbolAddress((void**)&wpq,   g_wpq);
    cudaGetSymbolAddress((void**)&wpk,   g_wpk);
    cudaGetSymbolAddress((void**)&qp,    g_qp);
    cudaGetSymbolAddress((void**)&kp,    g_kp);
    cudaGetSymbolAddress((void**)&v,     g_v);
    cudaGetSymbolAddress((void**)&ob,    g_ob);
    cudaGetSymbolAddress((void**)&bqf,   g_bq);
    cudaGetSymbolAddress((void**)&bkf,   g_bk);
    cudaGetSymbolAddress((void**)&bpart, g_bpart);
    cudaGetSymbolAddress((void**)&fpart, g_fpart);

    const int NX = MROWS * E_DIM;
    const int NW = E_DIM * E_DIM;

    cudaFuncSetAttribute(hgemm_bf16<0>,   cudaFuncAttributeMaxDynamicSharedMemorySize, GEMM_SMEM);
    cudaFuncSetAttribute(hgemm_fold_part, cudaFuncAttributeMaxDynamicSharedMemorySize, GEMM_SMEM);
    cudaFuncSetAttribute(hgemm_qkv,       cudaFuncAttributeMaxDynamicSharedMemorySize, GEMM_SMEM);
    cudaFuncSetAttribute(flash_bf16,      cudaFuncAttributeMaxDynamicSharedMemorySize, FLASH_SMEM);

    // 0) converts + bias folds
    conv_split3<<<dim3(384, 1, 3), 256>>>(x, xb, NX, qkvw + 2u * NW, wv, NW, outw, wout, NW);
    convT_split4<<<dim3(32, 32, 4), dim3(32, 8)>>>(
        rot, rotT, ent, entT, qkvw, wqT, qkvw + 1u * NW, wkT);
    bias_fold_part<<<dim3(4, 16, 2), 256>>>(qkvb, rot, qkvb + E_DIM, ent, bpart);
    bias_fold_red<<<dim3(4, 1, 2), 256>>>(bpart, bqf, 0.125f, bkf, 1.f);

    // 0c) split-K weight folds (3-term) + reduce
    hgemm_fold_part<<<dim3(8, 8, 4), 256, GEMM_SMEM>>>(rotT, entT, wqT, wkT, fpart);
    fold_red<<<dim3(192, 1, 2), 256>>>(fpart, wpq, 0.125f, wpk, 1.f);

    // 1) fused qkv GEMM (2-term) -> Q (rotated+scaled), K (entangled), V planes
    hgemm_qkv<<<dim3(3 * E_DIM / 128, MROWS / 128), 256, GEMM_SMEM>>>(
        xb, xb + NX,
        wpq, wpq + NW, wpk, wpk + NW, wv, wv + NW,
        bqf, bkf, qkvb + 2 * E_DIM,
        qp, qp + NX, kp, kp + NX, v, v + NX);

    // 2) attention -> O planes
    flash_bf16<<<dim3(SEQ / 64, NHEAD, BATCH), 128, FLASH_SMEM>>>(
        qp, qp + NX, kp, kp + NX, v, v + NX, ob, ob + NX);

    // 3) out = O @ out_w^T + out_b + x  (2-term)
    hgemm_bf16<0><<<dim3(E_DIM / 128, MROWS / 128), 256, GEMM_SMEM>>>(
        ob, ob + NX, E_DIM, wout, wout + NW, E_DIM,
        outb, x, E_DIM, out, E_DIM,
        nullptr, nullptr, 0, 1.f, E_DIM);
}